// round 3
// baseline (speedup 1.0000x reference)
#include <cuda_runtime.h>
#include <cuda_fp16.h>
#include <cstdint>

#define KC    64            // number of selected columns
#define DCOL  1024          // columns of x
#define NTRI  2016          // upper-triangular terms
#define NEVEN 1024          // terms with even i (packed first)
#define NM3   512
#define NM4   512
#define NM5   512
#define TPB   128           // threads per block
#define ROWS_PER_BLOCK 64   // 2 threads per row in phase A
#define NPAIR 32            // row-pairs per block
#define NBLOCKS 512         // 512 * 64 rows = 32768

// -------- persistent scratch (no allocations allowed) --------
__device__ float    g_tri[NTRI];     // packed triu(b,1): even-i rows [0,1024), odd-i rows [1024,2016)
__device__ uint2    g_rec3[NM3];     // x: i0|i1<<8|i2<<16, y: c bits
__device__ uint2    g_rec4[NM4];     // x: i0..i3 packed bytes, y: c bits
__device__ uint4    g_rec5[NM5];     // x: i0..i3 bytes, y: i4, z: c bits, w: pad
__device__ float    g_a[KC];
__device__ unsigned g_xoff[KC];      // S[k]

// -------- prep kernel --------
__global__ void prep_kernel(const float* __restrict__ b,
                            const int*   __restrict__ S,
                            const float* __restrict__ a,
                            const int*   __restrict__ idx3, const float* __restrict__ c3,
                            const int*   __restrict__ idx4, const float* __restrict__ c4,
                            const int*   __restrict__ idx5, const float* __restrict__ c5)
{
    int t = blockIdx.x * blockDim.x + threadIdx.x;
    if (t < NTRI) {
        // linear triangular index -> (i, j)
        int rem = t, i = 0;
        while (rem >= 63 - i) { rem -= 63 - i; ++i; }
        int j = i + 1 + rem;
        // split by i parity: even-i rows packed at [0,1024), odd-i at [1024,2016)
        int m = i >> 1;
        int dst = ((i & 1) == 0) ? (m * (64 - m) + (j - i - 1))
                                 : (NEVEN + m * (63 - m) + (j - i - 1));
        g_tri[dst] = b[i * 64 + j];
    }
    if (t < NM3) {
        unsigned p = (unsigned)idx3[t*3+0] | ((unsigned)idx3[t*3+1] << 8)
                   | ((unsigned)idx3[t*3+2] << 16);
        uint2 r; r.x = p; r.y = __float_as_uint(c3[t]);
        g_rec3[t] = r;
    }
    if (t < NM4) {
        unsigned p = (unsigned)idx4[t*4+0] | ((unsigned)idx4[t*4+1] << 8)
                   | ((unsigned)idx4[t*4+2] << 16) | ((unsigned)idx4[t*4+3] << 24);
        uint2 r; r.x = p; r.y = __float_as_uint(c4[t]);
        g_rec4[t] = r;
    }
    if (t < NM5) {
        unsigned p = (unsigned)idx5[t*5+0] | ((unsigned)idx5[t*5+1] << 8)
                   | ((unsigned)idx5[t*5+2] << 16) | ((unsigned)idx5[t*5+3] << 24);
        uint4 r; r.x = p; r.y = (unsigned)idx5[t*5+4];
        r.z = __float_as_uint(c5[t]); r.w = 0u;
        g_rec5[t] = r;
    }
    if (t < KC) {
        g_a[t]    = a[t];
        g_xoff[t] = (unsigned)S[t];
    }
}

// half the quadratic form: rows of the triangle with i ≡ H (mod 2),
// coefficients streamed contiguously from the reordered packed array.
template<int H>
__device__ __forceinline__ float quad_half(const float* __restrict__ s_tri,
                                           const float (&xv)[KC])
{
    const float4* tri4 = (const float4*)s_tri;
    float4 tb = make_float4(0.f, 0.f, 0.f, 0.f);
    float acc = 0.f;
    int p = H ? NEVEN : 0;
    #pragma unroll
    for (int i = H; i < KC - 1; i += 2) {
        float s = 0.f;
        #pragma unroll
        for (int j = i + 1; j < KC; ++j) {
            if ((p & 3) == 0) tb = tri4[p >> 2];
            float bv = ((p & 3) == 0) ? tb.x :
                       ((p & 3) == 1) ? tb.y :
                       ((p & 3) == 2) ? tb.z : tb.w;
            s = fmaf(bv, xv[j], s);
            ++p;
        }
        acc = fmaf(s, xv[i], acc);
    }
    return acc;
}

// -------- main kernel --------
__global__ __launch_bounds__(TPB)
void poly_kernel(const float* __restrict__ x, float* __restrict__ out)
{
    __shared__ float    s_tri[NTRI];               // 8064 B
    __shared__ uint2    s_rec3[NM3];               // 4 KB
    __shared__ uint2    s_rec4[NM4];               // 4 KB
    __shared__ uint4    s_rec5[NM5];               // 8 KB
    __shared__ float    s_a[KC];
    __shared__ unsigned s_xi[KC];
    __shared__ __half   s_x[KC][ROWS_PER_BLOCK];   // [64][64] half = 8 KB, row stride 128B
    __shared__ float    s_q[2][ROWS_PER_BLOCK];    // quad/lin partials
    __shared__ float2   s_red[4][NPAIR];           // monomial partials

    const int tid = threadIdx.x;

    // cooperative preload of coefficients into shared
    {
        const float4* ts = (const float4*)g_tri;
        float4*       td = (float4*)s_tri;
        #pragma unroll 1
        for (int i = tid; i < NTRI/4; i += TPB) td[i] = ts[i];
        #pragma unroll 1
        for (int i = tid; i < NM3; i += TPB) s_rec3[i] = g_rec3[i];
        #pragma unroll 1
        for (int i = tid; i < NM4; i += TPB) s_rec4[i] = g_rec4[i];
        #pragma unroll 1
        for (int i = tid; i < NM5; i += TPB) s_rec5[i] = g_rec5[i];
        if (tid < KC) { s_a[tid] = g_a[tid]; s_xi[tid] = g_xoff[tid]; }
    }
    __syncthreads();

    // ---------------- phase A: 2 threads per row ----------------------------
    const int row = tid & (ROWS_PER_BLOCK - 1);    // 0..63
    const int h   = tid >> 6;                      // column half 0/1 (warp-uniform)
    const long long grow = (long long)blockIdx.x * ROWS_PER_BLOCK + row;
    const float* xr = x + grow * DCOL;

    float xv[KC];

    // gather own 32 columns (exact fp32, kept in regs) + publish fp16
    if (h == 0) {
        #pragma unroll
        for (int k = 0; k < 32; ++k) xv[k] = __ldg(xr + s_xi[k]);
        #pragma unroll
        for (int k = 0; k < 32; ++k) s_x[k][row] = __float2half(xv[k]);
    } else {
        #pragma unroll
        for (int k = 32; k < KC; ++k) xv[k] = __ldg(xr + s_xi[k]);
        #pragma unroll
        for (int k = 32; k < KC; ++k) s_x[k][row] = __float2half(xv[k]);
    }
    __syncthreads();

    // fetch the other half from the fp16 tile
    if (h == 0) {
        #pragma unroll
        for (int k = 32; k < KC; ++k) xv[k] = __half2float(s_x[k][row]);
    } else {
        #pragma unroll
        for (int k = 0; k < 32; ++k) xv[k] = __half2float(s_x[k][row]);
    }

    // quadratic form split by i-parity; linear term on the h=1 thread
    {
        float a0;
        if (h == 0) {
            a0 = quad_half<0>(s_tri, xv);
        } else {
            float l = 0.f;
            #pragma unroll
            for (int k = 0; k < KC; ++k) l = fmaf(s_a[k], xv[k], l);
            a0 = l + quad_half<1>(s_tri, xv);
        }
        s_q[h][row] = a0;
    }

    // ---------------- phase B: monomials, 4 threads per row-pair ------------
    const int pr = tid & (NPAIR - 1);   // pair id 0..31
    const int q  = tid >> 5;            // term quarter 0..3 (warp-uniform)
    // pair pr covers rows (2pr, 2pr+1); row stride = 128B -> offset = idx<<7
    const char* xb = (const char*)(&s_x[0][0]) + 4 * pr;
    float m0 = 0.f, m1 = 0.f;

    {
        const int lo = q * (NM3 / 4), hi = lo + (NM3 / 4);
        #pragma unroll 4
        for (int t3 = lo; t3 < hi; ++t3) {
            uint2 r = s_rec3[t3];
            unsigned o0 = (r.x << 7) & 0x3F80u;
            unsigned o1 = (r.x >> 1) & 0x3F80u;
            unsigned o2 = (r.x >> 9) & 0x3F80u;
            __half2 prd = __hmul2(*(const __half2*)(xb + o0),
                                  *(const __half2*)(xb + o1));
            prd = __hmul2(prd, *(const __half2*)(xb + o2));
            float2 pf = __half22float2(prd);
            float c = __uint_as_float(r.y);
            m0 = fmaf(c, pf.x, m0);
            m1 = fmaf(c, pf.y, m1);
        }
    }
    {
        const int lo = q * (NM4 / 4), hi = lo + (NM4 / 4);
        #pragma unroll 4
        for (int t4 = lo; t4 < hi; ++t4) {
            uint2 r = s_rec4[t4];
            unsigned o0 = (r.x << 7)  & 0x3F80u;
            unsigned o1 = (r.x >> 1)  & 0x3F80u;
            unsigned o2 = (r.x >> 9)  & 0x3F80u;
            unsigned o3 = (r.x >> 17) & 0x3F80u;
            __half2 p01 = __hmul2(*(const __half2*)(xb + o0),
                                  *(const __half2*)(xb + o1));
            __half2 p23 = __hmul2(*(const __half2*)(xb + o2),
                                  *(const __half2*)(xb + o3));
            __half2 prd = __hmul2(p01, p23);
            float2 pf = __half22float2(prd);
            float c = __uint_as_float(r.y);
            m0 = fmaf(c, pf.x, m0);
            m1 = fmaf(c, pf.y, m1);
        }
    }
    {
        const int lo = q * (NM5 / 4), hi = lo + (NM5 / 4);
        #pragma unroll 4
        for (int t5 = lo; t5 < hi; ++t5) {
            uint4 r = s_rec5[t5];
            unsigned o0 = (r.x << 7)  & 0x3F80u;
            unsigned o1 = (r.x >> 1)  & 0x3F80u;
            unsigned o2 = (r.x >> 9)  & 0x3F80u;
            unsigned o3 = (r.x >> 17) & 0x3F80u;
            unsigned o4 =  r.y << 7;
            __half2 p01 = __hmul2(*(const __half2*)(xb + o0),
                                  *(const __half2*)(xb + o1));
            __half2 p23 = __hmul2(*(const __half2*)(xb + o2),
                                  *(const __half2*)(xb + o3));
            __half2 prd = __hmul2(__hmul2(p01, p23),
                                  *(const __half2*)(xb + o4));
            float2 pf = __half22float2(prd);
            float c = __uint_as_float(r.z);
            m0 = fmaf(c, pf.x, m0);
            m1 = fmaf(c, pf.y, m1);
        }
    }

    s_red[q][pr] = make_float2(m0, m1);
    __syncthreads();

    if (tid < NPAIR) {
        float2 r0 = s_red[0][tid];
        float2 r1 = s_red[1][tid];
        float2 r2 = s_red[2][tid];
        float2 r3 = s_red[3][tid];
        float2 o2v;
        o2v.x = s_q[0][2*tid+0] + s_q[1][2*tid+0] + r0.x + r1.x + r2.x + r3.x;
        o2v.y = s_q[0][2*tid+1] + s_q[1][2*tid+1] + r0.y + r1.y + r2.y + r3.y;
        ((float2*)out)[blockIdx.x * NPAIR + tid] = o2v;
    }
}

// -------- launch --------
extern "C" void kernel_launch(void* const* d_in, const int* in_sizes, int n_in,
                              void* d_out, int out_size)
{
    const float* x    = (const float*)d_in[0];
    const int*   S    = (const int*)  d_in[1];
    const float* a    = (const float*)d_in[2];
    const float* b    = (const float*)d_in[3];
    const int*   idx3 = (const int*)  d_in[4];
    const float* c3   = (const float*)d_in[5];
    const int*   idx4 = (const int*)  d_in[6];
    const float* c4   = (const float*)d_in[7];
    const int*   idx5 = (const int*)  d_in[8];
    const float* c5   = (const float*)d_in[9];
    float* out = (float*)d_out;

    prep_kernel<<<8, 256>>>(b, S, a, idx3, c3, idx4, c4, idx5, c5);
    poly_kernel<<<NBLOCKS, TPB>>>(x, out);
}

// round 4
// speedup vs baseline: 1.3345x; 1.3345x over previous
#include <cuda_runtime.h>
#include <cuda_fp16.h>
#include <cstdint>

#define KC    64            // number of selected columns
#define DCOL  1024          // columns of x
#define NTRI  2016          // upper-triangular terms
#define NM3   512
#define NM4   512
#define NM5   512
#define TPB   128           // threads per block
#define ROWS_PER_BLOCK 128  // 1 row per thread in phase A
#define NGROUP 32           // 4-row groups per block (phase B)
#define NBLOCKS 256         // 256 * 128 rows = 32768

// -------- persistent scratch (no allocations allowed) --------
__device__ float    g_tri[NTRI];     // packed triu(b,1), row-major (i asc, j asc)
__device__ uint2    g_rec3[NM3];     // x: i0|i1<<8|i2<<16, y: c bits
__device__ uint2    g_rec4[NM4];     // x: i0..i3 packed bytes, y: c bits
__device__ uint4    g_rec5[NM5];     // x: i0..i3 bytes, y: i4, z: c bits, w: pad
__device__ float    g_a[KC];
__device__ unsigned g_xoff[KC];      // S[k]

// -------- prep kernel --------
__global__ void prep_kernel(const float* __restrict__ b,
                            const int*   __restrict__ S,
                            const float* __restrict__ a,
                            const int*   __restrict__ idx3, const float* __restrict__ c3,
                            const int*   __restrict__ idx4, const float* __restrict__ c4,
                            const int*   __restrict__ idx5, const float* __restrict__ c5)
{
    int t = blockIdx.x * blockDim.x + threadIdx.x;
    if (t < NTRI) {
        // linear triangular index -> (i, j), same static order the main kernel unrolls
        int rem = t, i = 0;
        while (rem >= 63 - i) { rem -= 63 - i; ++i; }
        int j = i + 1 + rem;
        g_tri[t] = b[i * 64 + j];
    }
    if (t < NM3) {
        unsigned p = (unsigned)idx3[t*3+0] | ((unsigned)idx3[t*3+1] << 8)
                   | ((unsigned)idx3[t*3+2] << 16);
        uint2 r; r.x = p; r.y = __float_as_uint(c3[t]);
        g_rec3[t] = r;
    }
    if (t < NM4) {
        unsigned p = (unsigned)idx4[t*4+0] | ((unsigned)idx4[t*4+1] << 8)
                   | ((unsigned)idx4[t*4+2] << 16) | ((unsigned)idx4[t*4+3] << 24);
        uint2 r; r.x = p; r.y = __float_as_uint(c4[t]);
        g_rec4[t] = r;
    }
    if (t < NM5) {
        unsigned p = (unsigned)idx5[t*5+0] | ((unsigned)idx5[t*5+1] << 8)
                   | ((unsigned)idx5[t*5+2] << 16) | ((unsigned)idx5[t*5+3] << 24);
        uint4 r; r.x = p; r.y = (unsigned)idx5[t*5+4];
        r.z = __float_as_uint(c5[t]); r.w = 0u;
        g_rec5[t] = r;
    }
    if (t < KC) {
        g_a[t]    = a[t];
        g_xoff[t] = (unsigned)S[t];
    }
}

__device__ __forceinline__ __half2 as_h2(unsigned u) {
    __half2 h;
    *reinterpret_cast<unsigned*>(&h) = u;
    return h;
}

// -------- main kernel: 1 row/thread quad, 4-row-group monomials -------------
__global__ __launch_bounds__(TPB)
void poly_kernel(const float* __restrict__ x, float* __restrict__ out)
{
    __shared__ float    s_tri[NTRI];               // 8064 B
    __shared__ uint2    s_rec3[NM3];               // 4 KB
    __shared__ uint2    s_rec4[NM4];               // 4 KB
    __shared__ uint4    s_rec5[NM5];               // 8 KB
    __shared__ float    s_a[KC];
    __shared__ unsigned s_xi[KC];
    __shared__ __half   s_x[KC][ROWS_PER_BLOCK];   // [64][128] half = 16 KB, row stride 256B
    __shared__ float    s_acc[ROWS_PER_BLOCK];     // per-row lin+quad
    __shared__ float    s_redf[4][ROWS_PER_BLOCK]; // monomial partials (quarter x row)

    const int tid = threadIdx.x;

    // cooperative preload of coefficients into shared
    {
        const float4* ts = (const float4*)g_tri;
        float4*       td = (float4*)s_tri;
        #pragma unroll 1
        for (int i = tid; i < NTRI/4; i += TPB) td[i] = ts[i];
        #pragma unroll 1
        for (int i = tid; i < NM3; i += TPB) s_rec3[i] = g_rec3[i];
        #pragma unroll 1
        for (int i = tid; i < NM4; i += TPB) s_rec4[i] = g_rec4[i];
        #pragma unroll 1
        for (int i = tid; i < NM5; i += TPB) s_rec5[i] = g_rec5[i];
        if (tid < KC) { s_a[tid] = g_a[tid]; s_xi[tid] = g_xoff[tid]; }
    }
    __syncthreads();

    // ---------------- phase A: gather + linear + quadratic (fp32, registers) --
    {
        const long long row = (long long)blockIdx.x * ROWS_PER_BLOCK + tid;
        const float* xr = x + row * DCOL;
        float xv[KC];
        #pragma unroll
        for (int k = 0; k < KC; ++k) xv[k] = __ldg(xr + s_xi[k]);

        float a0 = 0.f;
        #pragma unroll
        for (int k = 0; k < KC; ++k) a0 = fmaf(s_a[k], xv[k], a0);

        // quadratic form: fully unrolled triangular loop, x in registers,
        // packed-tri coefficients via broadcast LDS.128
        {
            const float4* tri4 = (const float4*)s_tri;
            float4 tb = make_float4(0.f, 0.f, 0.f, 0.f);
            int p = 0;
            #pragma unroll
            for (int i = 0; i < KC - 1; ++i) {
                float s = 0.f;
                #pragma unroll
                for (int j = i + 1; j < KC; ++j) {
                    if ((p & 3) == 0) tb = tri4[p >> 2];
                    float bv = ((p & 3) == 0) ? tb.x :
                               ((p & 3) == 1) ? tb.y :
                               ((p & 3) == 2) ? tb.z : tb.w;
                    s = fmaf(bv, xv[j], s);
                    ++p;
                }
                a0 = fmaf(s, xv[i], a0);
            }
        }
        s_acc[tid] = a0;

        // publish fp16 copy for the monomial phase
        #pragma unroll
        for (int k = 0; k < KC; ++k)
            s_x[k][tid] = __float2half(xv[k]);
    }
    __syncthreads();

    // ---------------- phase B: monomials on 4-row groups ---------------------
    // group g covers rows (4g..4g+3); one LDS.64 fetches an operand for all 4.
    const int g = tid & (NGROUP - 1);   // group id 0..31
    const int q = tid >> 5;             // term quarter 0..3 (warp-uniform)
    const char* xb = (const char*)(&s_x[0][0]) + 8 * g;  // operand offset = idx<<8
    float m0 = 0.f, m1 = 0.f, m2 = 0.f, m3 = 0.f;

    {
        const int lo = q * (NM3 / 4), hi = lo + (NM3 / 4);
        #pragma unroll 4
        for (int t3 = lo; t3 < hi; ++t3) {
            uint2 r = s_rec3[t3];
            unsigned o0 = (r.x << 8) & 0xFF00u;
            unsigned o1 =  r.x       & 0xFF00u;
            unsigned o2 = (r.x >> 8) & 0xFF00u;
            uint2 u0 = *(const uint2*)(xb + o0);
            uint2 u1 = *(const uint2*)(xb + o1);
            uint2 u2 = *(const uint2*)(xb + o2);
            __half2 pa = __hmul2(__hmul2(as_h2(u0.x), as_h2(u1.x)), as_h2(u2.x));
            __half2 pb = __hmul2(__hmul2(as_h2(u0.y), as_h2(u1.y)), as_h2(u2.y));
            float2 fa = __half22float2(pa);
            float2 fb = __half22float2(pb);
            float c = __uint_as_float(r.y);
            m0 = fmaf(c, fa.x, m0);
            m1 = fmaf(c, fa.y, m1);
            m2 = fmaf(c, fb.x, m2);
            m3 = fmaf(c, fb.y, m3);
        }
    }
    {
        const int lo = q * (NM4 / 4), hi = lo + (NM4 / 4);
        #pragma unroll 4
        for (int t4 = lo; t4 < hi; ++t4) {
            uint2 r = s_rec4[t4];
            unsigned o0 = (r.x << 8)  & 0xFF00u;
            unsigned o1 =  r.x        & 0xFF00u;
            unsigned o2 = (r.x >> 8)  & 0xFF00u;
            unsigned o3 = (r.x >> 16) & 0xFF00u;
            uint2 u0 = *(const uint2*)(xb + o0);
            uint2 u1 = *(const uint2*)(xb + o1);
            uint2 u2 = *(const uint2*)(xb + o2);
            uint2 u3 = *(const uint2*)(xb + o3);
            __half2 pa = __hmul2(__hmul2(as_h2(u0.x), as_h2(u1.x)),
                                 __hmul2(as_h2(u2.x), as_h2(u3.x)));
            __half2 pb = __hmul2(__hmul2(as_h2(u0.y), as_h2(u1.y)),
                                 __hmul2(as_h2(u2.y), as_h2(u3.y)));
            float2 fa = __half22float2(pa);
            float2 fb = __half22float2(pb);
            float c = __uint_as_float(r.y);
            m0 = fmaf(c, fa.x, m0);
            m1 = fmaf(c, fa.y, m1);
            m2 = fmaf(c, fb.x, m2);
            m3 = fmaf(c, fb.y, m3);
        }
    }
    {
        const int lo = q * (NM5 / 4), hi = lo + (NM5 / 4);
        #pragma unroll 4
        for (int t5 = lo; t5 < hi; ++t5) {
            uint4 r = s_rec5[t5];
            unsigned o0 = (r.x << 8)  & 0xFF00u;
            unsigned o1 =  r.x        & 0xFF00u;
            unsigned o2 = (r.x >> 8)  & 0xFF00u;
            unsigned o3 = (r.x >> 16) & 0xFF00u;
            unsigned o4 =  r.y << 8;
            uint2 u0 = *(const uint2*)(xb + o0);
            uint2 u1 = *(const uint2*)(xb + o1);
            uint2 u2 = *(const uint2*)(xb + o2);
            uint2 u3 = *(const uint2*)(xb + o3);
            uint2 u4 = *(const uint2*)(xb + o4);
            __half2 pa = __hmul2(__hmul2(__hmul2(as_h2(u0.x), as_h2(u1.x)),
                                         __hmul2(as_h2(u2.x), as_h2(u3.x))),
                                 as_h2(u4.x));
            __half2 pb = __hmul2(__hmul2(__hmul2(as_h2(u0.y), as_h2(u1.y)),
                                         __hmul2(as_h2(u2.y), as_h2(u3.y))),
                                 as_h2(u4.y));
            float2 fa = __half22float2(pa);
            float2 fb = __half22float2(pb);
            float c = __uint_as_float(r.z);
            m0 = fmaf(c, fa.x, m0);
            m1 = fmaf(c, fa.y, m1);
            m2 = fmaf(c, fb.x, m2);
            m3 = fmaf(c, fb.y, m3);
        }
    }

    // s_redf[q][4g..4g+3] = partials for the 4 rows of group g
    *(float4*)&s_redf[q][4 * g] = make_float4(m0, m1, m2, m3);
    __syncthreads();

    // one thread per row combines quad + 4 monomial quarters
    {
        float r = s_acc[tid]
                + s_redf[0][tid] + s_redf[1][tid]
                + s_redf[2][tid] + s_redf[3][tid];
        out[blockIdx.x * ROWS_PER_BLOCK + tid] = r;
    }
}

// -------- launch --------
extern "C" void kernel_launch(void* const* d_in, const int* in_sizes, int n_in,
                              void* d_out, int out_size)
{
    const float* x    = (const float*)d_in[0];
    const int*   S    = (const int*)  d_in[1];
    const float* a    = (const float*)d_in[2];
    const float* b    = (const float*)d_in[3];
    const int*   idx3 = (const int*)  d_in[4];
    const float* c3   = (const float*)d_in[5];
    const int*   idx4 = (const int*)  d_in[6];
    const float* c4   = (const float*)d_in[7];
    const int*   idx5 = (const int*)  d_in[8];
    const float* c5   = (const float*)d_in[9];
    float* out = (float*)d_out;

    prep_kernel<<<8, 256>>>(b, S, a, idx3, c3, idx4, c4, idx5, c5);
    poly_kernel<<<NBLOCKS, TPB>>>(x, out);
}